// round 16
// baseline (speedup 1.0000x reference)
#include <cuda_runtime.h>
#include <cuda_fp16.h>
#include <cstdint>

// ---------------- problem dims ----------------
#define B_   32
#define T_   4096
#define DIN_ 256
#define H_   256
#define BT_  (B_ * T_)

// ---------------- fused tiling ------------------
#define TCH   128             // tokens per chunk
#define NCHK  (T_ / TCH)      // 32 chunks
#define HSL   64              // h channels per CTA slice
#define NPROD 512             // producer threads (16 warps)
#define NTHR  544             // + 1 consumer warp

// smem layout (bytes)
#define SM_A     0                  // 4 K-panels x 16384 (full chunk: 128 tok x 256 halves)
#define SM_W     65536              // 4 K-panels x 16384 (W: 64 z-rows + 64 h-rows)
#define SM_CV    131072             // DOUBLE buffer: 2 x (128 tok x 64 h x half2) = 2 x 32768
#define SMEM_FUSED 196608

// cv smem swizzle: half2 index for (token t, channel h)
#define CVIDX(t, h) ((t) * 64 + ((h) ^ (((t) & 7) << 3)))
#define CVBUF 8192   // half2 entries per buffer

// named barriers: 1,2 = full[buf]; 3,4 = empty[buf]; 5 = producer-only
#define BAR_SYNC(id, cnt)   asm volatile("bar.sync %0, %1;"   :: "r"(id), "r"(cnt) : "memory")
#define BAR_ARRIVE(id, cnt) asm volatile("bar.arrive %0, %1;" :: "r"(id), "r"(cnt) : "memory")

// ---------------- scratch ----------------------
__device__ __half g_Xh[(size_t)BT_ * DIN_];

// ---------------- fp32 -> fp16 convert (X only) ----------------
__global__ void __launch_bounds__(256) convert_kernel(const float* __restrict__ X)
{
    const size_t i = (size_t)blockIdx.x * blockDim.x + threadIdx.x;
    const size_t stride = (size_t)gridDim.x * blockDim.x;
    const size_t XF4 = (size_t)BT_ * DIN_ / 4;

    const float4* X4 = reinterpret_cast<const float4*>(X);
    uint2* OX = reinterpret_cast<uint2*>(g_Xh);
    for (size_t j = i; j < XF4; j += stride) {
        float4 v = X4[j];
        __half2 h0 = __floats2half2_rn(v.x, v.y);
        __half2 h1 = __floats2half2_rn(v.z, v.w);
        OX[j] = make_uint2(*reinterpret_cast<uint32_t*>(&h0), *reinterpret_cast<uint32_t*>(&h1));
    }
}

// ---------------- helpers ------------------
__device__ __forceinline__ uint32_t smem_u32(const void* p) {
    uint32_t r;
    asm("{\n\t.reg .u64 t;\n\tcvta.to.shared.u64 t, %1;\n\tcvt.u32.u64 %0, t;\n\t}"
        : "=r"(r) : "l"(p));
    return r;
}
__device__ __forceinline__ void cp16(uint32_t dst, const void* src) {
    asm volatile("cp.async.cg.shared.global [%0], [%1], 16;" :: "r"(dst), "l"(src));
}
#define CP_COMMIT()  asm volatile("cp.async.commit_group;" ::: "memory")
#define CP_WAIT0()   asm volatile("cp.async.wait_group 0;" ::: "memory")
#define SWZ(o) ((o) ^ ((((uint32_t)(o)) >> 3) & 0x70))

__device__ __forceinline__ void ldm_x4(uint32_t& r0, uint32_t& r1, uint32_t& r2, uint32_t& r3,
                                       uint32_t addr) {
    asm volatile("ldmatrix.sync.aligned.m8n8.x4.shared.b16 {%0,%1,%2,%3}, [%4];"
                 : "=r"(r0), "=r"(r1), "=r"(r2), "=r"(r3) : "r"(addr));
}
__device__ __forceinline__ void mma_f16(float* d, const uint32_t* a, uint32_t b0, uint32_t b1) {
    asm volatile("mma.sync.aligned.m16n8k16.row.col.f32.f16.f16.f32 "
                 "{%0,%1,%2,%3}, {%4,%5,%6,%7}, {%8,%9}, {%0,%1,%2,%3};"
                 : "+f"(d[0]), "+f"(d[1]), "+f"(d[2]), "+f"(d[3])
                 : "r"(a[0]), "r"(a[1]), "r"(a[2]), "r"(a[3]), "r"(b0), "r"(b1));
}

__device__ __forceinline__ float tanh_fast(float x) {
    float t;
    asm("tanh.approx.f32 %0, %1;" : "=f"(t) : "f"(x));
    return t;
}
__device__ __forceinline__ void zc_pair(float k, float& z, float& c) {
    float t = tanh_fast(0.5f * k);
    z = fmaf(0.5f, t, 0.5f);
    c = fmaf(-0.5f, t, 0.5f);
}
__device__ __forceinline__ float g_act(float x) {
    if (x >= 0.f) return x + 0.5f;
    float t = tanh_fast(0.5f * x);
    return fmaf(0.5f, t, 0.5f);
}
__device__ __forceinline__ uint32_t pack_h2(float a, float b) {
    __half2 p = __floats2half2_rn(a, b);
    return *reinterpret_cast<uint32_t*>(&p);
}

// ---------------- fused GEMM + activation (producers) | scan (consumer) ----------------
// grid: (slice [0,4), batch [0,32)); block 544 = 16 GEMM warps (4Mx4N) + 1 scan warp
__global__ void __launch_bounds__(NTHR, 1) fused_kernel(
    const float* __restrict__ Wz, const float* __restrict__ bz,
    const float* __restrict__ Wh, const float* __restrict__ bh,
    const float* __restrict__ h0g, float* __restrict__ out)
{
    extern __shared__ char smem[];
    const uint32_t sbase = smem_u32(smem);

    __half2*  scvH = reinterpret_cast<__half2*>(smem + SM_CV);
    uint32_t* scvU = reinterpret_cast<uint32_t*>(smem + SM_CV);

    const int tid  = threadIdx.x;
    const int lane = tid & 31;
    const int wid  = tid >> 5;

    const int slice = blockIdx.x;
    const int b     = blockIdx.y;
    const int hbase = slice * HSL;

    const uint4* Xh16 = reinterpret_cast<const uint4*>(g_Xh);

    // ---- chunk loader (producers only; tid < 512) ----
    auto ld_chunk = [&](int c) {
        const size_t tok0 = (size_t)b * T_ + (size_t)c * TCH;
        #pragma unroll
        for (int i = 0; i < 8; i++) {
            int q = tid + i * NPROD;        // 0..4095
            int r = q >> 5;                 // token row 0..127
            int u = q & 31;                 // 16B unit within 512B row
            int p = u >> 3, uu = u & 7;     // K-panel, unit within panel
            cp16(sbase + SM_A + p * 16384 + SWZ(r * 128 + uu * 16),
                 Xh16 + (tok0 + r) * 32 + u);
        }
    };

    // ---- prologue (producers): W fp32->fp16 swizzled smem + chunk 0 ----
    if (tid < NPROD) {
        const float4* Wz4f = reinterpret_cast<const float4*>(Wz);
        const float4* Wh4f = reinterpret_cast<const float4*>(Wh);
        #pragma unroll
        for (int i = 0; i < 8; i++) {
            int q = tid + i * NPROD;
            int c = q >> 10, rem = q & 1023;
            int r = rem >> 3, u = rem & 7;
            const float4* src = (r < 64) ? (Wz4f + (size_t)(hbase + r) * 64 + c * 16 + u * 2)
                                         : (Wh4f + (size_t)(hbase + r - 64) * 64 + c * 16 + u * 2);
            float4 f0 = src[0], f1 = src[1];
            uint4 o = make_uint4(pack_h2(f0.x, f0.y), pack_h2(f0.z, f0.w),
                                 pack_h2(f1.x, f1.y), pack_h2(f1.z, f1.w));
            *reinterpret_cast<uint4*>(smem + SM_W + c * 16384 + SWZ(r * 128 + u * 16)) = o;
        }
        ld_chunk(0); CP_COMMIT();
        CP_WAIT0();
    }
    __syncthreads();   // uniform: prologue visible to all

    if (tid < NPROD) {
        // =================== PRODUCERS: GEMM + activation ===================
        const int wm   = wid >> 2;    // 0..3 (token dir)
        const int wn   = wid & 3;     // 0..3 (h dir)
        const int grp  = lane >> 2;
        const int tg   = lane & 3;
        const int lrow = ((lane >> 3) & 1) * 8 + (lane & 7);
        const int lkh  = (lane >> 4) * 16;

        float bzr[2][2], bhr[2][2];
        #pragma unroll
        for (int nt = 0; nt < 2; nt++) {
            int col = hbase + wn * 16 + nt * 8 + 2 * tg;
            bzr[nt][0] = bz[col];     bzr[nt][1] = bz[col + 1];
            bhr[nt][0] = bh[col];     bhr[nt][1] = bh[col + 1];
        }

        float accZ[2][2][4], accH[2][2][4];
        #pragma unroll
        for (int mt = 0; mt < 2; mt++)
            #pragma unroll
            for (int nt = 0; nt < 2; nt++)
                #pragma unroll
                for (int q = 0; q < 4; q++) { accZ[mt][nt][q] = 0.f; accH[mt][nt][q] = 0.f; }

        #pragma unroll 1
        for (int chunk = 0; chunk < NCHK; chunk++) {
            // ---- GEMM: 16 uninterrupted ks iterations ----
            #pragma unroll
            for (int ks = 0; ks < 16; ks++) {
                const uint32_t aB = sbase + SM_A + (ks >> 2) * 16384;
                const uint32_t wB = sbase + SM_W + (ks >> 2) * 16384;
                const int kb = (ks & 3) * 32 + lkh;
                uint32_t a[2][4], z[4], hh[4];
                #pragma unroll
                for (int mt = 0; mt < 2; mt++)
                    ldm_x4(a[mt][0], a[mt][1], a[mt][2], a[mt][3],
                           aB + SWZ((wm * 32 + mt * 16 + lrow) * 128 + kb));
                ldm_x4(z[0], z[1], z[2], z[3],
                       wB + SWZ((wn * 16 + lrow) * 128 + kb));
                ldm_x4(hh[0], hh[1], hh[2], hh[3],
                       wB + SWZ((64 + wn * 16 + lrow) * 128 + kb));
                #pragma unroll
                for (int mt = 0; mt < 2; mt++)
                    #pragma unroll
                    for (int nt = 0; nt < 2; nt++) {
                        mma_f16(accZ[mt][nt], a[mt], z[nt], z[nt + 2]);
                        mma_f16(accH[mt][nt], a[mt], hh[nt], hh[nt + 2]);
                    }
            }
            BAR_SYNC(5, NPROD);                   // all A reads of this chunk done

            if (chunk + 1 < NCHK) { ld_chunk(chunk + 1); CP_COMMIT(); }
            else                  { CP_COMMIT(); }

            // wait for consumer to free this cv buffer (steady state: no wait)
            if (chunk >= 2) BAR_SYNC(3 + (chunk & 1), NTHR);

            // ---- activation -> cv[buf] ----
            uint32_t* dst = scvU + (chunk & 1) * (2 * CVBUF) / 2;  // CVBUF half2 = CVBUF u32*? careful
            dst = scvU + (chunk & 1) * CVBUF;   // half2 entries == u32 entries
            #pragma unroll
            for (int mt = 0; mt < 2; mt++) {
                #pragma unroll
                for (int nt = 0; nt < 2; nt++) {
                    const int col = wn * 16 + nt * 8 + 2 * tg;
                    const int r0  = wm * 32 + mt * 16 + grp;
                    float k0  = accZ[mt][nt][0] + bzr[nt][0];
                    float k1  = accZ[mt][nt][1] + bzr[nt][1];
                    float k2  = accZ[mt][nt][2] + bzr[nt][0];
                    float k3  = accZ[mt][nt][3] + bzr[nt][1];
                    float kh0 = accH[mt][nt][0] + bhr[nt][0];
                    float kh1 = accH[mt][nt][1] + bhr[nt][1];
                    float kh2 = accH[mt][nt][2] + bhr[nt][0];
                    float kh3 = accH[mt][nt][3] + bhr[nt][1];
                    float z0, c0, z1, c1, z2, c2, z3, c3;
                    zc_pair(k0, z0, c0);
                    zc_pair(k1, z1, c1);
                    zc_pair(k2, z2, c2);
                    zc_pair(k3, z3, c3);
                    uint2 p0 = make_uint2(pack_h2(c0, z0 * g_act(kh0)),
                                          pack_h2(c1, z1 * g_act(kh1)));
                    uint2 p1 = make_uint2(pack_h2(c2, z2 * g_act(kh2)),
                                          pack_h2(c3, z3 * g_act(kh3)));
                    *reinterpret_cast<uint2*>(&dst[CVIDX(r0,     col)]) = p0;
                    *reinterpret_cast<uint2*>(&dst[CVIDX(r0 + 8, col)]) = p1;
                }
            }
            __threadfence_block();
            BAR_ARRIVE(1 + (chunk & 1), NTHR);    // cv[buf] full

            CP_WAIT0();
            BAR_SYNC(5, NPROD);                   // next A visible to all producers

            #pragma unroll
            for (int mt = 0; mt < 2; mt++)
                #pragma unroll
                for (int nt = 0; nt < 2; nt++)
                    #pragma unroll
                    for (int q = 0; q < 4; q++) { accZ[mt][nt][q] = 0.f; accH[mt][nt][q] = 0.f; }
        }
    } else {
        // =================== CONSUMER: serial scan, 2 channels/thread ===================
        const int ch0 = lane;
        const int ch1 = lane + 32;

        // exact h0 transform (one-off)
        float x0 = h0g[b * H_ + hbase + ch0];
        float x1 = h0g[b * H_ + hbase + ch1];
        float hv0 = (x0 >= 0.f) ? (x0 + 0.5f) : __fdividef(1.f, 1.f + __expf(-x0));
        float hv1 = (x1 >= 0.f) ? (x1 + 0.5f) : __fdividef(1.f, 1.f + __expf(-x1));

        #pragma unroll 1
        for (int chunk = 0; chunk < NCHK; chunk++) {
            BAR_SYNC(1 + (chunk & 1), NTHR);      // wait cv[buf] full
            const __half2* cvb = scvH + (chunk & 1) * CVBUF;
            float* ob = out + ((size_t)b * T_ + (size_t)chunk * TCH) * H_ + hbase;
            #pragma unroll 4
            for (int t = 0; t < TCH; t++) {
                float2 f0 = __half22float2(cvb[CVIDX(t, ch0)]);
                float2 f1 = __half22float2(cvb[CVIDX(t, ch1)]);
                hv0 = fmaf(f0.x, hv0, f0.y);
                hv1 = fmaf(f1.x, hv1, f1.y);
                ob[(size_t)t * H_ + ch0] = hv0;
                ob[(size_t)t * H_ + ch1] = hv1;
            }
            BAR_ARRIVE(3 + (chunk & 1), NTHR);    // cv[buf] free
        }
    }
}

// ---------------- launch -------------------------------------------------
extern "C" void kernel_launch(void* const* d_in, const int* in_sizes, int n_in,
                              void* d_out, int out_size)
{
    const float* x  = (const float*)d_in[0];
    const float* h0 = (const float*)d_in[1];
    const float* Wz = (const float*)d_in[2];
    const float* bz = (const float*)d_in[3];
    const float* Wh = (const float*)d_in[4];
    const float* bh = (const float*)d_in[5];
    float* out = (float*)d_out;

    convert_kernel<<<512, 256>>>(x);

    cudaFuncSetAttribute(fused_kernel, cudaFuncAttributeMaxDynamicSharedMemorySize, SMEM_FUSED);
    dim3 fgrid(H_ / HSL, B_);            // (4, 32) = 128 CTAs
    fused_kernel<<<fgrid, NTHR, SMEM_FUSED>>>(Wz, bz, Wh, bh, h0, out);
}

// round 17
// speedup vs baseline: 1.1031x; 1.1031x over previous
#include <cuda_runtime.h>
#include <cuda_fp16.h>
#include <cstdint>

// ---------------- problem dims ----------------
#define B_   32
#define T_   4096
#define DIN_ 256
#define H_   256
#define BT_  (B_ * T_)

// ---------------- fused tiling ------------------
#define TCH   128             // tokens per chunk
#define NCHK  (T_ / TCH)      // 32 chunks
#define HSL   64              // h channels per CTA slice

// smem layout (bytes)
#define SM_A     0                  // 4 K-panels x 16384 (full chunk: 128 tok x 256 halves)
#define SM_W     65536              // 4 K-panels x 16384 (W: 64 z-rows + 64 h-rows)
#define SM_CV    131072             // 128 tok x 64 h x half2 = 32768
#define SM_SEGP  163840             // 8 x 64 floats
#define SM_SEGS  165888             // 8 x 64 floats
#define SM_HC    167936             // 2 x 64 floats carry (ping-pong)
#define SMEM_FUSED 168448

// cv smem swizzle: word index for (token t, channel h)
#define CVIDX(t, h) ((t) * 64 + ((h) ^ (((t) & 7) << 3)))

// ---------------- scratch ----------------------
__device__ __half g_Xh[(size_t)BT_ * DIN_];

// ---------------- fp32 -> fp16 convert (X only) ----------------
__global__ void __launch_bounds__(256) convert_kernel(const float* __restrict__ X)
{
    const size_t i = (size_t)blockIdx.x * blockDim.x + threadIdx.x;
    const size_t stride = (size_t)gridDim.x * blockDim.x;
    const size_t XF4 = (size_t)BT_ * DIN_ / 4;

    const float4* X4 = reinterpret_cast<const float4*>(X);
    uint2* OX = reinterpret_cast<uint2*>(g_Xh);
    for (size_t j = i; j < XF4; j += stride) {
        float4 v = X4[j];
        __half2 h0 = __floats2half2_rn(v.x, v.y);
        __half2 h1 = __floats2half2_rn(v.z, v.w);
        OX[j] = make_uint2(*reinterpret_cast<uint32_t*>(&h0), *reinterpret_cast<uint32_t*>(&h1));
    }
}

// ---------------- helpers ------------------
__device__ __forceinline__ uint32_t smem_u32(const void* p) {
    uint32_t r;
    asm("{\n\t.reg .u64 t;\n\tcvta.to.shared.u64 t, %1;\n\tcvt.u32.u64 %0, t;\n\t}"
        : "=r"(r) : "l"(p));
    return r;
}
__device__ __forceinline__ void cp16(uint32_t dst, const void* src) {
    asm volatile("cp.async.cg.shared.global [%0], [%1], 16;" :: "r"(dst), "l"(src));
}
#define CP_COMMIT()  asm volatile("cp.async.commit_group;" ::: "memory")
#define CP_WAIT0()   asm volatile("cp.async.wait_group 0;" ::: "memory")
#define SWZ(o) ((o) ^ ((((uint32_t)(o)) >> 3) & 0x70))

__device__ __forceinline__ void ldm_x4(uint32_t& r0, uint32_t& r1, uint32_t& r2, uint32_t& r3,
                                       uint32_t addr) {
    asm volatile("ldmatrix.sync.aligned.m8n8.x4.shared.b16 {%0,%1,%2,%3}, [%4];"
                 : "=r"(r0), "=r"(r1), "=r"(r2), "=r"(r3) : "r"(addr));
}
__device__ __forceinline__ void mma_f16(float* d, const uint32_t* a, uint32_t b0, uint32_t b1) {
    asm volatile("mma.sync.aligned.m16n8k16.row.col.f32.f16.f16.f32 "
                 "{%0,%1,%2,%3}, {%4,%5,%6,%7}, {%8,%9}, {%0,%1,%2,%3};"
                 : "+f"(d[0]), "+f"(d[1]), "+f"(d[2]), "+f"(d[3])
                 : "r"(a[0]), "r"(a[1]), "r"(a[2]), "r"(a[3]), "r"(b0), "r"(b1));
}

__device__ __forceinline__ float tanh_fast(float x) {
    float t;
    asm("tanh.approx.f32 %0, %1;" : "=f"(t) : "f"(x));
    return t;
}
__device__ __forceinline__ void zc_pair(float k, float& z, float& c) {
    float t = tanh_fast(0.5f * k);
    z = fmaf(0.5f, t, 0.5f);
    c = fmaf(-0.5f, t, 0.5f);
}
__device__ __forceinline__ float g_act(float x) {
    if (x >= 0.f) return x + 0.5f;
    float t = tanh_fast(0.5f * x);
    return fmaf(0.5f, t, 0.5f);
}
__device__ __forceinline__ uint32_t pack_h2(float a, float b) {
    __half2 p = __floats2half2_rn(a, b);
    return *reinterpret_cast<uint32_t*>(&p);
}

// ---------------- fused GEMM + activation + scan ----------------
// grid: (slice [0,4), batch [0,32)); block 512 = 16 warps laid out 4(M) x 4(N)
__global__ void __launch_bounds__(512, 1) fused_kernel(
    const float* __restrict__ Wz, const float* __restrict__ bz,
    const float* __restrict__ Wh, const float* __restrict__ bh,
    const float* __restrict__ h0g, float* __restrict__ out)
{
    extern __shared__ char smem[];
    const uint32_t sbase = smem_u32(smem);

    float*   segP = reinterpret_cast<float*>(smem + SM_SEGP);
    float*   segS = reinterpret_cast<float*>(smem + SM_SEGS);
    float*   hcF  = reinterpret_cast<float*>(smem + SM_HC);   // [2][64] ping-pong
    __half2* scvH = reinterpret_cast<__half2*>(smem + SM_CV);
    uint32_t* scvU = reinterpret_cast<uint32_t*>(smem + SM_CV);

    const int tid  = threadIdx.x;
    const int lane = tid & 31;
    const int wid  = tid >> 5;
    const int wm   = wid >> 2;    // 0..3 (token dir, 32 rows each)
    const int wn   = wid & 3;     // 0..3 (h dir, 16 cols each)
    const int grp  = lane >> 2;   // 0..7
    const int tg   = lane & 3;    // 0..3
    const int lrow = ((lane >> 3) & 1) * 8 + (lane & 7);
    const int lkh  = (lane >> 4) * 16;

    const int slice = blockIdx.x;
    const int b     = blockIdx.y;
    const int hbase = slice * HSL;

    // scan-phase mapping
    const int seg = tid >> 6;      // 0..7, 16 tokens each
    const int hch = tid & 63;      // h channel within slice

    // init h carry slot 0 (exact one-off transform)
    if (tid < HSL) {
        float x = h0g[b * H_ + hbase + tid];
        hcF[tid] = (x >= 0.f) ? (x + 0.5f)
                              : __fdividef(1.f, 1.f + __expf(-x));
    }

    // bias preload
    float bzr[2][2], bhr[2][2];
    #pragma unroll
    for (int nt = 0; nt < 2; nt++) {
        int col = hbase + wn * 16 + nt * 8 + 2 * tg;
        bzr[nt][0] = bz[col];     bzr[nt][1] = bz[col + 1];
        bhr[nt][0] = bh[col];     bhr[nt][1] = bh[col + 1];
    }

    const float4* Wz4f = reinterpret_cast<const float4*>(Wz);
    const float4* Wh4f = reinterpret_cast<const float4*>(Wh);
    const uint4*  Xh16 = reinterpret_cast<const uint4*>(g_Xh);

    // ---- prologue: convert this CTA's W slice fp32 -> fp16 swizzled smem ----
    #pragma unroll
    for (int i = 0; i < 8; i++) {
        int q = tid + i * 512;
        int c = q >> 10, rem = q & 1023;
        int r = rem >> 3, u = rem & 7;
        const float4* src = (r < 64) ? (Wz4f + (size_t)(hbase + r) * 64 + c * 16 + u * 2)
                                     : (Wh4f + (size_t)(hbase + r - 64) * 64 + c * 16 + u * 2);
        float4 f0 = src[0], f1 = src[1];
        uint4 o = make_uint4(pack_h2(f0.x, f0.y), pack_h2(f0.z, f0.w),
                             pack_h2(f1.x, f1.y), pack_h2(f1.z, f1.w));
        *reinterpret_cast<uint4*>(smem + SM_W + c * 16384 + SWZ(r * 128 + u * 16)) = o;
    }

    // ---- chunk loader: full 128 tok x 256 halves (64KB) via cp.async ----
    auto ld_chunk = [&](int c) {
        const size_t tok0 = (size_t)b * T_ + (size_t)c * TCH;
        #pragma unroll
        for (int i = 0; i < 8; i++) {
            int q = tid + i * 512;          // 0..4095
            int r = q >> 5;                 // token row 0..127
            int u = q & 31;                 // 16B unit within 512B row
            int p = u >> 3, uu = u & 7;     // K-panel, unit within panel
            cp16(sbase + SM_A + p * 16384 + SWZ(r * 128 + uu * 16),
                 Xh16 + (tok0 + r) * 32 + u);
        }
    };

    float accZ[2][2][4], accH[2][2][4];
    #pragma unroll
    for (int mt = 0; mt < 2; mt++)
        #pragma unroll
        for (int nt = 0; nt < 2; nt++)
            #pragma unroll
            for (int q = 0; q < 4; q++) { accZ[mt][nt][q] = 0.f; accH[mt][nt][q] = 0.f; }

    ld_chunk(0); CP_COMMIT();
    CP_WAIT0();
    __syncthreads();   // W prologue + chunk 0 + hcF[0] visible

    #pragma unroll 1
    for (int chunk = 0; chunk < NCHK; chunk++) {
        // ---- GEMM: full chunk, 16 uninterrupted ks iterations ----
        #pragma unroll
        for (int ks = 0; ks < 16; ks++) {
            const uint32_t aB = sbase + SM_A + (ks >> 2) * 16384;
            const uint32_t wB = sbase + SM_W + (ks >> 2) * 16384;
            const int kb = (ks & 3) * 32 + lkh;
            uint32_t a[2][4], z[4], hh[4];
            #pragma unroll
            for (int mt = 0; mt < 2; mt++)
                ldm_x4(a[mt][0], a[mt][1], a[mt][2], a[mt][3],
                       aB + SWZ((wm * 32 + mt * 16 + lrow) * 128 + kb));
            ldm_x4(z[0], z[1], z[2], z[3],
                   wB + SWZ((wn * 16 + lrow) * 128 + kb));
            ldm_x4(hh[0], hh[1], hh[2], hh[3],
                   wB + SWZ((64 + wn * 16 + lrow) * 128 + kb));
            #pragma unroll
            for (int mt = 0; mt < 2; mt++)
                #pragma unroll
                for (int nt = 0; nt < 2; nt++) {
                    mma_f16(accZ[mt][nt], a[mt], z[nt], z[nt + 2]);
                    mma_f16(accH[mt][nt], a[mt], hh[nt], hh[nt + 2]);
                }
        }
        __syncthreads();   // all A reads of this chunk done (accs are in regs)

        // ---- prefetch next chunk NOW: overlaps activation + whole scan ----
        if (chunk + 1 < NCHK) { ld_chunk(chunk + 1); CP_COMMIT(); }

        // ---- activation -> cv smem (tanh-based) ----
        #pragma unroll
        for (int mt = 0; mt < 2; mt++) {
            #pragma unroll
            for (int nt = 0; nt < 2; nt++) {
                const int col = wn * 16 + nt * 8 + 2 * tg;   // local h
                const int r0  = wm * 32 + mt * 16 + grp;     // local token
                float k0  = accZ[mt][nt][0] + bzr[nt][0];
                float k1  = accZ[mt][nt][1] + bzr[nt][1];
                float k2  = accZ[mt][nt][2] + bzr[nt][0];
                float k3  = accZ[mt][nt][3] + bzr[nt][1];
                float kh0 = accH[mt][nt][0] + bhr[nt][0];
                float kh1 = accH[mt][nt][1] + bhr[nt][1];
                float kh2 = accH[mt][nt][2] + bhr[nt][0];
                float kh3 = accH[mt][nt][3] + bhr[nt][1];
                float z0, c0, z1, c1, z2, c2, z3, c3;
                zc_pair(k0, z0, c0);
                zc_pair(k1, z1, c1);
                zc_pair(k2, z2, c2);
                zc_pair(k3, z3, c3);
                uint2 p0 = make_uint2(pack_h2(c0, z0 * g_act(kh0)),
                                      pack_h2(c1, z1 * g_act(kh1)));
                uint2 p1 = make_uint2(pack_h2(c2, z2 * g_act(kh2)),
                                      pack_h2(c3, z3 * g_act(kh3)));
                *reinterpret_cast<uint2*>(&scvU[CVIDX(r0,     col)]) = p0;
                *reinterpret_cast<uint2*>(&scvU[CVIDX(r0 + 8, col)]) = p1;
            }
        }
        __syncthreads();   // cv visible

        // ---- segment aggregate (16 tokens per thread) ----
        float P = 1.f, S = 0.f;
        const int tokb = seg * 16;
        #pragma unroll
        for (int j = 0; j < 16; j++) {
            float2 cv = __half22float2(scvH[CVIDX(tokb + j, hch)]);
            S = fmaf(cv.x, S, cv.y);
            P *= cv.x;
        }
        segP[seg * 64 + hch] = P;
        segS[seg * 64 + hch] = S;
        __syncthreads();

        // ---- combine: prefix over segments + carry (ping-pong slots) ----
        float hin = hcF[(chunk & 1) * 64 + hch];
        #pragma unroll
        for (int q = 0; q < 7; q++)
            if (q < seg) hin = fmaf(segP[q * 64 + hch], hin, segS[q * 64 + hch]);
        // no barrier: seg7 writes the OTHER carry slot

        // ---- replay + emit ----
        float hv = hin;
        size_t obase = ((size_t)b * T_ + (size_t)chunk * TCH + tokb) * H_ + hbase + hch;
        #pragma unroll
        for (int j = 0; j < 16; j++) {
            float2 cv = __half22float2(scvH[CVIDX(tokb + j, hch)]);
            hv = fmaf(cv.x, hv, cv.y);
            out[obase + (size_t)j * H_] = hv;
        }
        if (seg == 7) hcF[((chunk + 1) & 1) * 64 + hch] = hv;

        CP_WAIT0();        // next chunk's A resident
        __syncthreads();   // carry + cv/segP reuse safe + A visible

        // reset accumulators
        #pragma unroll
        for (int mt = 0; mt < 2; mt++)
            #pragma unroll
            for (int nt = 0; nt < 2; nt++)
                #pragma unroll
                for (int q = 0; q < 4; q++) { accZ[mt][nt][q] = 0.f; accH[mt][nt][q] = 0.f; }
    }
}

// ---------------- launch -------------------------------------------------
extern "C" void kernel_launch(void* const* d_in, const int* in_sizes, int n_in,
                              void* d_out, int out_size)
{
    const float* x  = (const float*)d_in[0];
    const float* h0 = (const float*)d_in[1];
    const float* Wz = (const float*)d_in[2];
    const float* bz = (const float*)d_in[3];
    const float* Wh = (const float*)d_in[4];
    const float* bh = (const float*)d_in[5];
    float* out = (float*)d_out;

    convert_kernel<<<512, 256>>>(x);

    cudaFuncSetAttribute(fused_kernel, cudaFuncAttributeMaxDynamicSharedMemorySize, SMEM_FUSED);
    dim3 fgrid(H_ / HSL, B_);            // (4, 32) = 128 CTAs
    fused_kernel<<<fgrid, 512, SMEM_FUSED>>>(Wz, bz, Wh, bh, h0, out);
}